// round 6
// baseline (speedup 1.0000x reference)
#include <cuda_runtime.h>
#include <cstdint>
#include <math.h>

#define NUMB   4
#define PRE    1024
#define CAND   4096
#define HBINS  65536
#define MAXN   200000
#define TOPK   2048

// ---------------- device scratch (static, no runtime alloc) ----------------
__device__ unsigned long long g_keyarr[MAXN];
__device__ unsigned           g_hist[NUMB][HBINS];
__device__ unsigned           g_thr[NUMB];
__device__ int                g_ccnt[NUMB];
__device__ unsigned long long g_cand[NUMB][CAND];
__device__ unsigned long long g_prec[NUMB][CAND];
__device__ unsigned long long g_sel[NUMB][PRE];
__device__ float              g_boxes[NUMB][PRE][8];
__device__ unsigned           g_mask[NUMB][PRE][32];
__device__ unsigned           g_rowflag[NUMB][32];

__device__ __forceinline__ float exp_cr(float x)  { return (float)exp((double)x); }
__device__ __forceinline__ float atan2_cr(float y, float x) {
    return (float)atan2((double)y, (double)x);
}

// ---------------- K0: zero hist / cand / counters / flags ----------------
__global__ void k_init() {
    int i = blockIdx.x * 256 + threadIdx.x;           // grid covers 262144
    ((unsigned*)g_hist)[i] = 0;                        // NUMB*HBINS == 262144
    if (i < NUMB * CAND * 2) ((unsigned*)g_cand)[i] = 0;
    if (i < NUMB) { g_ccnt[i] = 0; }
    if (i < NUMB * 32) ((unsigned*)g_rowflag)[i] = 0;
}

// ---------------- K1: APPROX score pass + histogram ----------------------
// 16 lanes per point, 2 points per warp-iteration; 4 independent float4
// loads per lane in flight -> high MLP, full-line coalescing.
__global__ void __launch_bounds__(256) k_score(
        const float* __restrict__ feat,
        const int*   __restrict__ bidx,
        const float* __restrict__ Wc,
        const float* __restrict__ bc,
        const float* __restrict__ Wr,
        const float* __restrict__ br,
        int N) {
    const int warp = threadIdx.x >> 5;
    const int lane = threadIdx.x & 31;
    const int j    = lane & 15;        // lane within point
    const int sub  = lane >> 4;        // which of the 2 points

    // weights for this lane's 16 features: f = 4*(j + 16*q) + e
    float wd[4][4], w8[4][4];
#pragma unroll
    for (int q = 0; q < 4; q++) {
#pragma unroll
        for (int e = 0; e < 4; e++) {
            int f = 4 * (j + 16 * q) + e;
            wd[q][e] = Wc[f * 2 + 1] - Wc[f * 2 + 0];
            w8[q][e] = Wr[f * 9 + 8];
        }
    }
    const float bd  = bc[1] - bc[0];
    const float b8r = br[8];

    const int base0 = blockIdx.x * 256 + warp * 32;

#pragma unroll 2
    for (int it = 0; it < 16; it++) {
        int p = base0 + it * 2 + sub;
        bool ok = (p < N);
        float4 v0, v1, v2, v3;
        if (ok) {
            const float4* f4 = (const float4*)(feat + (size_t)p * 256);
            v0 = f4[j];
            v1 = f4[j + 16];
            v2 = f4[j + 32];
            v3 = f4[j + 48];
        } else {
            v0 = v1 = v2 = v3 = make_float4(0.f, 0.f, 0.f, 0.f);
        }
        float accd, accr;
        {
            float d0 = v0.x * wd[0][0] + v0.y * wd[0][1] + v0.z * wd[0][2] + v0.w * wd[0][3];
            float d1 = v1.x * wd[1][0] + v1.y * wd[1][1] + v1.z * wd[1][2] + v1.w * wd[1][3];
            float d2 = v2.x * wd[2][0] + v2.y * wd[2][1] + v2.z * wd[2][2] + v2.w * wd[2][3];
            float d3 = v3.x * wd[3][0] + v3.y * wd[3][1] + v3.z * wd[3][2] + v3.w * wd[3][3];
            accd = (d0 + d1) + (d2 + d3);
            float r0 = v0.x * w8[0][0] + v0.y * w8[0][1] + v0.z * w8[0][2] + v0.w * w8[0][3];
            float r1 = v1.x * w8[1][0] + v1.y * w8[1][1] + v1.z * w8[1][2] + v1.w * w8[1][3];
            float r2 = v2.x * w8[2][0] + v2.y * w8[2][1] + v2.z * w8[2][2] + v2.w * w8[2][3];
            float r3 = v3.x * w8[3][0] + v3.y * w8[3][1] + v3.z * w8[3][2] + v3.w * w8[3][3];
            accr = (r0 + r1) + (r2 + r3);
        }
#pragma unroll
        for (int o = 8; o > 0; o >>= 1) {
            accd += __shfl_xor_sync(0xffffffffu, accd, o);
            accr += __shfl_xor_sync(0xffffffffu, accr, o);
        }
        if (j == 0 && ok) {
            float s = 1.0f / ((1.0f + expf(-(accd + bd))) * (1.0f + expf(-(accr + b8r))));
            unsigned sb = __float_as_uint(s);
            g_keyarr[p] = ((unsigned long long)sb << 32) | (unsigned)(~(unsigned)p);
            atomicAdd(&g_hist[bidx[p]][sb >> 16], 1u);
        }
    }
}

// ---------------- K2: per-batch threshold from histogram ------------------
__global__ void k_thresh() {
    const int b = blockIdx.x;
    const int t = threadIdx.x;
    __shared__ int sm[1024];
    const unsigned* h = g_hist[b];
    const int base = t * 64;

    int s = 0;
#pragma unroll 8
    for (int i = 0; i < 64; i++) s += (int)h[base + i];
    sm[t] = s;
    __syncthreads();
    for (int off = 1; off < 1024; off <<= 1) {
        int v = (t + off < 1024) ? sm[t + off] : 0;
        __syncthreads();
        sm[t] += v;
        __syncthreads();
    }

    if (sm[0] < TOPK) {
        if (t == 0) g_thr[b] = 0u;
        return;
    }
    bool found = (sm[t] >= TOPK) && (t == 1023 || sm[t + 1] < TOPK);
    if (found) {
        int acc = (t < 1023) ? sm[t + 1] : 0;
        int B = base;
        for (int i = 63; i >= 0; i--) {
            acc += (int)h[base + i];
            if (acc >= TOPK) { B = base + i; break; }
        }
        g_thr[b] = ((unsigned)B) << 16;
    }
}

// ---------------- K3: compact candidates >= threshold (4 pts/thread) ------
__global__ void k_compact(const int* __restrict__ bidx, int N) {
    int base = (blockIdx.x * 256 + threadIdx.x) * 4;
    if (base >= N) return;
    unsigned long long key[4];
    int bb[4];
    int n = min(4, N - base);
#pragma unroll
    for (int k = 0; k < 4; k++) {
        if (k < n) {
            key[k] = g_keyarr[base + k];
            bb[k]  = bidx[base + k];
        }
    }
#pragma unroll
    for (int k = 0; k < 4; k++) {
        if (k < n && (unsigned)(key[k] >> 32) >= g_thr[bb[k]]) {
            int slot = atomicAdd(&g_ccnt[bb[k]], 1);
            if (slot < CAND) g_cand[bb[k]][slot] = key[k];
        }
    }
}

// ---------------- K4: PRECISE rescore of candidates -----------------------
__global__ void __launch_bounds__(128) k_rescore(
        const float* __restrict__ feat,
        const float* __restrict__ Wc,
        const float* __restrict__ bc,
        const float* __restrict__ Wr,
        const float* __restrict__ br,
        int N) {
    __shared__ float swc0[256], swc1[256], sw8[256];
    for (int i = threadIdx.x; i < 256; i += 128) {
        swc0[i] = Wc[2 * i + 0];
        swc1[i] = Wc[2 * i + 1];
        sw8[i]  = Wr[9 * i + 8];
    }
    __syncthreads();

    const int b = blockIdx.y;
    const int warp = threadIdx.x >> 5;
    const int lane = threadIdx.x & 31;
    const int k = blockIdx.x * 4 + warp;

    unsigned long long key = g_cand[b][k];
    unsigned idx = ~(unsigned)(key & 0xffffffffu);
    bool valid = (idx < (unsigned)N);

    double d0 = 0.0, d1 = 0.0, d2 = 0.0;
    if (valid) {
        const float4* f4 = (const float4*)(feat + (size_t)idx * 256);
        float4 a  = f4[lane * 2 + 0];
        float4 c4 = f4[lane * 2 + 1];
        float fv[8] = {a.x, a.y, a.z, a.w, c4.x, c4.y, c4.z, c4.w};
        const float* wp[3] = {&swc0[lane * 8], &swc1[lane * 8], &sw8[lane * 8]};
        double* dp[3] = {&d0, &d1, &d2};
#pragma unroll
        for (int o = 0; o < 3; o++) {
            float s = 0.0f, comp = 0.0f;
#pragma unroll
            for (int c = 0; c < 8; c++) {
                float v = fv[c], w = wp[o][c];
                float p = __fmul_rn(v, w);
                float e = __fmaf_rn(v, w, -p);      // exact product tail
                float t = __fadd_rn(s, p);          // Knuth TwoSum
                float bv = __fadd_rn(t, -s);
                float c1 = __fadd_rn(s, -__fadd_rn(t, -bv));
                float c2 = __fadd_rn(p, -bv);
                comp = __fadd_rn(comp, __fadd_rn(c1, c2));
                comp = __fadd_rn(comp, e);
                s = t;
            }
            *dp[o] = (double)s + (double)comp;
        }
    }
#pragma unroll
    for (int o = 16; o > 0; o >>= 1) {
        d0 += __shfl_xor_sync(0xffffffffu, d0, o);
        d1 += __shfl_xor_sync(0xffffffffu, d1, o);
        d2 += __shfl_xor_sync(0xffffffffu, d2, o);
    }

    if (lane == 0) {
        unsigned long long outk = 0ull;
        if (valid) {
            double l0 = d0 + (double)bc[0];
            double l1 = d1 + (double)bc[1];
            double r8 = d2 + (double)br[8];
            double m  = fmax(l0, l1);
            double e0 = exp(l0 - m);
            double e1 = exp(l1 - m);
            double conf = e1 / (e0 + e1);
            double scr  = 1.0 / (1.0 + exp(-r8));
            float sf = (float)(conf * scr);
            outk = ((unsigned long long)__float_as_uint(sf) << 32) |
                   (unsigned)(key & 0xffffffffu);
        }
        g_prec[b][k] = outk;
    }
}

// ---------------- K5: re-rank 4096 precise keys -> top 1024 ---------------
__global__ void k_rank() {
    const int b = blockIdx.x;
    const int t = threadIdx.x;
    __shared__ unsigned long long s[CAND];
#pragma unroll
    for (int rr = 0; rr < 4; rr++) s[t + rr * 1024] = g_prec[b][t + rr * 1024];

    for (unsigned k = 2; k <= CAND; k <<= 1) {
        for (unsigned j = k >> 1; j > 0; j >>= 1) {
            __syncthreads();
#pragma unroll
            for (int rr = 0; rr < 4; rr++) {
                unsigned tt = t + rr * 1024;
                unsigned ixj = tt ^ j;
                if (ixj > tt) {
                    unsigned long long a = s[tt], bb = s[ixj];
                    bool desc = ((tt & k) == 0);
                    if (desc ? (a < bb) : (a > bb)) { s[tt] = bb; s[ixj] = a; }
                }
            }
        }
    }
    __syncthreads();
    g_sel[b][t] = s[t];
}

// ---------------- K6: decode boxes for selected 4096 points --------------
__global__ void __launch_bounds__(128) k_decode(
        const float* __restrict__ feat,
        const int*   __restrict__ coor,
        const float* __restrict__ Wr,
        const float* __restrict__ br,
        int N) {
    __shared__ float sW[256 * 9];
    __shared__ float srow[4][256];
    for (int i = threadIdx.x; i < 256 * 9; i += 128) sW[i] = Wr[i];
    __syncthreads();

    const int b = blockIdx.y;
    const int warp = threadIdx.x >> 5;
    const int lane = threadIdx.x & 31;
    const int k = blockIdx.x * 4 + warp;

    unsigned long long key = g_sel[b][k];
    unsigned idx = ~(unsigned)(key & 0xffffffffu);
    bool valid = (idx < (unsigned)N);
    if (!valid) idx = 0;

    {
        const float4* f4 = (const float4*)(feat + (size_t)idx * 256);
        float4 a = f4[lane * 2 + 0];
        float4 c4 = f4[lane * 2 + 1];
        ((float4*)srow[warp])[lane * 2 + 0] = a;
        ((float4*)srow[warp])[lane * 2 + 1] = c4;
    }
    __syncwarp();

    float acc = 0.0f;
    if (lane < 8) {
        const float* row = srow[warp];
#pragma unroll 8
        for (int kk = 0; kk < 256; kk++) {
            acc = __fmaf_rn(row[kk], sW[kk * 9 + lane], acc);
        }
        acc = __fadd_rn(acc, br[lane]);
    }

    float r[8];
#pragma unroll
    for (int j = 0; j < 8; j++) r[j] = __shfl_sync(0xffffffffu, acc, j);

    if (lane == 0) {
        float out[8];
        if (valid) {
            float cx = __fmul_rn((float)coor[(size_t)idx * 2 + 0], 0.8f);
            float cy = __fmul_rn((float)coor[(size_t)idx * 2 + 1], 0.8f);
            out[0] = __fadd_rn(cx, r[0]);
            out[1] = __fadd_rn(cy, r[1]);
            out[2] = r[2];
            out[3] = exp_cr(fminf(fmaxf(r[3], -6.0f), 6.0f));
            out[4] = exp_cr(fminf(fmaxf(r[4], -6.0f), 6.0f));
            out[5] = exp_cr(fminf(fmaxf(r[5], -6.0f), 6.0f));
            out[6] = atan2_cr(r[6], r[7]);
            out[7] = __uint_as_float((unsigned)(key >> 32));
        } else {
#pragma unroll
            for (int j = 0; j < 8; j++) out[j] = 0.0f;
        }
#pragma unroll
        for (int j = 0; j < 8; j++) g_boxes[b][k][j] = out[j];
    }
}

// ---------------- K7: IoU suppression bitmask (parallel) ------------------
__global__ void k_mask() {
    const int b = blockIdx.y;
    const int j = threadIdx.x;                 // column
    __shared__ float sx1[PRE], sx2[PRE], sy1[PRE], sy2[PRE], sa[PRE];

    float x = g_boxes[b][j][0], y = g_boxes[b][j][1];
    float l = g_boxes[b][j][3], w = g_boxes[b][j][4];
    bool jv = (~(unsigned)(g_sel[b][j] & 0xffffffffu)) < 0x7fffffffu;
    if (jv) {
        float lh = __fmul_rn(l, 0.5f);
        float wh = __fmul_rn(w, 0.5f);
        sx1[j] = __fadd_rn(x, -lh); sx2[j] = __fadd_rn(x, lh);
        sy1[j] = __fadd_rn(y, -wh); sy2[j] = __fadd_rn(y, wh);
        sa[j]  = __fmul_rn(l, w);
    } else {
        sx1[j] = 1e30f; sx2[j] = -1e30f;
        sy1[j] = 1e30f; sy2[j] = -1e30f;
        sa[j]  = 0.0f;
    }
    __syncthreads();

    const int i0 = blockIdx.x * 32;
    const float X1 = sx1[j], X2 = sx2[j], Y1 = sy1[j], Y2 = sy2[j], A = sa[j];
    for (int ii = 0; ii < 32; ii++) {
        int i = i0 + ii;
        float ix = fmaxf(__fadd_rn(fminf(sx2[i], X2), -fmaxf(sx1[i], X1)), 0.0f);
        float iy = fmaxf(__fadd_rn(fminf(sy2[i], Y2), -fmaxf(sy1[i], Y1)), 0.0f);
        float inter = __fmul_rn(ix, iy);
        float uni = __fadd_rn(__fadd_rn(sa[i], A), -inter);
        float iou = __fdiv_rn(inter, fmaxf(uni, 1e-6f));
        bool s = (j > i) && (iou > 0.1f);
        unsigned bal = __ballot_sync(0xffffffffu, s);
        if ((j & 31) == 0) {
            g_mask[b][i][j >> 5] = bal;
            if (bal) atomicOr(&g_rowflag[b][i >> 5], 1u << (i & 31));
        }
    }
}

// ---------------- K8: serial greedy scan (sparse rows only) + outputs -----
__global__ void k_scan_out(float* __restrict__ dout, int out_size) {
    const int b = blockIdx.x;
    const int t = threadIdx.x;
    __shared__ unsigned srem[32];

    if (t < 32) {
        unsigned rem = 0;
        unsigned flags = g_rowflag[b][t];
        for (int w = 0; w < 32; w++) {
            unsigned fw = __shfl_sync(0xffffffffu, flags, w);
            while (fw) {
                int bp = __ffs(fw) - 1;
                fw &= fw - 1;
                int i = w * 32 + bp;
                unsigned owner = __shfl_sync(0xffffffffu, rem, i >> 5);
                if (!((owner >> (i & 31)) & 1u)) {
                    rem |= g_mask[b][i][t];
                }
            }
        }
        srem[t] = rem;
    }
    __syncthreads();

    bool jv = (~(unsigned)(g_sel[b][t] & 0xffffffffu)) < 0x7fffffffu;
    bool keep = jv && !((srem[t >> 5] >> (t & 31)) & 1u);
    float kf = keep ? 1.0f : 0.0f;

    int obase = (b * PRE + t) * 8;
#pragma unroll
    for (int c = 0; c < 8; c++) {
        if (obase + c < out_size) dout[obase + c] = g_boxes[b][t][c] * kf;
    }
    int lbpos = NUMB * PRE * 8 + b * PRE + t;          // label section (always 0)
    if (lbpos < out_size) dout[lbpos] = 0.0f;
    int kppos = NUMB * PRE * 9 + b * PRE + t;          // keep section
    if (kppos < out_size) dout[kppos] = kf;
}

// ---------------- launcher ----------------
extern "C" void kernel_launch(void* const* d_in, const int* in_sizes, int n_in,
                              void* d_out, int out_size) {
    const float* feat  = (const float*)d_in[0];
    const int*   bidx  = (const int*)d_in[1];
    const int*   coor  = (const int*)d_in[2];
    const float* Wc    = (const float*)d_in[3];
    const float* bc    = (const float*)d_in[4];
    const float* Wr    = (const float*)d_in[5];
    const float* br    = (const float*)d_in[6];
    float* out = (float*)d_out;

    const int N = in_sizes[1];

    k_init<<<(NUMB * HBINS) / 256, 256>>>();
    k_score<<<(N + 255) / 256, 256>>>(feat, bidx, Wc, bc, Wr, br, N);
    k_thresh<<<NUMB, 1024>>>();
    k_compact<<<(N + 1023) / 1024, 256>>>(bidx, N);
    k_rescore<<<dim3(CAND / 4, NUMB), 128>>>(feat, Wc, bc, Wr, br, N);
    k_rank<<<NUMB, 1024>>>();
    k_decode<<<dim3(PRE / 4, NUMB), 128>>>(feat, coor, Wr, br, N);
    k_mask<<<dim3(PRE / 32, NUMB), 1024>>>();
    k_scan_out<<<NUMB, 1024>>>(out, out_size);
}

// round 7
// speedup vs baseline: 1.1884x; 1.1884x over previous
#include <cuda_runtime.h>
#include <cstdint>
#include <math.h>

#define NUMB   4
#define PRE    1024
#define CAND   4096
#define HBINS  65536
#define MAXN   200000
#define TOPK   2048

// ---------------- device scratch (static, no runtime alloc) ----------------
__device__ unsigned long long g_keyarr[MAXN];
__device__ unsigned           g_hist[NUMB][HBINS];
__device__ unsigned           g_thr[NUMB];
__device__ int                g_ccnt[NUMB];
__device__ unsigned long long g_cand[NUMB][CAND];
__device__ unsigned long long g_prec[NUMB][CAND];
__device__ unsigned long long g_tmp[NUMB][2048];
__device__ unsigned long long g_sel[NUMB][PRE];
__device__ float              g_boxes[NUMB][PRE][8];
__device__ unsigned           g_mask[NUMB][PRE][32];
__device__ unsigned           g_rowflag[NUMB][32];

__device__ __forceinline__ float exp_cr(float x)  { return (float)exp((double)x); }
__device__ __forceinline__ float atan2_cr(float y, float x) {
    return (float)atan2((double)y, (double)x);
}

// ---------------- K0a/b/c: zeroing (3 launches so k_score is launch #4) ---
__global__ void k_zero_hist() {          // 262144 uints via uint4
    int i = blockIdx.x * 256 + threadIdx.x;
    ((uint4*)g_hist)[i] = make_uint4(0, 0, 0, 0);
}
__global__ void k_zero_cand() {          // NUMB*CAND u64 = 8192 uint4
    int i = blockIdx.x * 256 + threadIdx.x;
    ((uint4*)g_cand)[i] = make_uint4(0, 0, 0, 0);
}
__global__ void k_zero_misc() {
    int t = threadIdx.x;
    if (t < NUMB) g_cnt_dummy: ;
    if (t < NUMB) g_ccnt[t] = 0;
    if (t < NUMB * 32) ((unsigned*)g_rowflag)[t] = 0;
}

// ---------------- K1: APPROX score pass + histogram (prefetch-pipelined) --
// 16 lanes per point, 2 points per warp-iteration; next iteration's 4
// float4 loads issued before current reduction -> 8 loads in flight/lane.
__global__ void __launch_bounds__(256) k_score(
        const float* __restrict__ feat,
        const int*   __restrict__ bidx,
        const float* __restrict__ Wc,
        const float* __restrict__ bc,
        const float* __restrict__ Wr,
        const float* __restrict__ br,
        int N) {
    const int warp = threadIdx.x >> 5;
    const int lane = threadIdx.x & 31;
    const int j    = lane & 15;        // lane within point
    const int sub  = lane >> 4;        // which of the 2 points

    float wd[4][4], w8[4][4];
#pragma unroll
    for (int q = 0; q < 4; q++) {
#pragma unroll
        for (int e = 0; e < 4; e++) {
            int f = 4 * (j + 16 * q) + e;
            wd[q][e] = Wc[f * 2 + 1] - Wc[f * 2 + 0];
            w8[q][e] = Wr[f * 9 + 8];
        }
    }
    const float bd  = bc[1] - bc[0];
    const float b8r = br[8];

    const int base0 = blockIdx.x * 256 + warp * 32;

    float4 c0, c1, c2, c3;
    {
        int p = base0 + sub;
        if (p < N) {
            const float4* f4 = (const float4*)(feat + (size_t)p * 256);
            c0 = f4[j]; c1 = f4[j + 16]; c2 = f4[j + 32]; c3 = f4[j + 48];
        } else {
            c0 = c1 = c2 = c3 = make_float4(0.f, 0.f, 0.f, 0.f);
        }
    }

    for (int it = 0; it < 16; it++) {
        float4 n0, n1, n2, n3;
        int pn = base0 + (it + 1) * 2 + sub;
        if (it < 15 && pn < N) {
            const float4* f4n = (const float4*)(feat + (size_t)pn * 256);
            n0 = f4n[j]; n1 = f4n[j + 16]; n2 = f4n[j + 32]; n3 = f4n[j + 48];
        } else {
            n0 = n1 = n2 = n3 = make_float4(0.f, 0.f, 0.f, 0.f);
        }

        float d0 = c0.x * wd[0][0] + c0.y * wd[0][1] + c0.z * wd[0][2] + c0.w * wd[0][3];
        float d1 = c1.x * wd[1][0] + c1.y * wd[1][1] + c1.z * wd[1][2] + c1.w * wd[1][3];
        float d2 = c2.x * wd[2][0] + c2.y * wd[2][1] + c2.z * wd[2][2] + c2.w * wd[2][3];
        float d3 = c3.x * wd[3][0] + c3.y * wd[3][1] + c3.z * wd[3][2] + c3.w * wd[3][3];
        float accd = (d0 + d1) + (d2 + d3);
        float r0 = c0.x * w8[0][0] + c0.y * w8[0][1] + c0.z * w8[0][2] + c0.w * w8[0][3];
        float r1 = c1.x * w8[1][0] + c1.y * w8[1][1] + c1.z * w8[1][2] + c1.w * w8[1][3];
        float r2 = c2.x * w8[2][0] + c2.y * w8[2][1] + c2.z * w8[2][2] + c2.w * w8[2][3];
        float r3 = c3.x * w8[3][0] + c3.y * w8[3][1] + c3.z * w8[3][2] + c3.w * w8[3][3];
        float accr = (r0 + r1) + (r2 + r3);

#pragma unroll
        for (int o = 8; o > 0; o >>= 1) {
            accd += __shfl_xor_sync(0xffffffffu, accd, o);
            accr += __shfl_xor_sync(0xffffffffu, accr, o);
        }
        int p_cur = base0 + it * 2 + sub;
        if (j == 0 && p_cur < N) {
            float s = 1.0f / ((1.0f + expf(-(accd + bd))) * (1.0f + expf(-(accr + b8r))));
            unsigned sb = __float_as_uint(s);
            g_keyarr[p_cur] = ((unsigned long long)sb << 32) | (unsigned)(~(unsigned)p_cur);
            atomicAdd(&g_hist[bidx[p_cur]][sb >> 16], 1u);
        }
        c0 = n0; c1 = n1; c2 = n2; c3 = n3;
    }
}

// ---------------- K2: per-batch threshold from histogram ------------------
__global__ void k_thresh() {
    const int b = blockIdx.x;
    const int t = threadIdx.x;
    __shared__ int sm[1024];
    const unsigned* h = g_hist[b];
    const int base = t * 64;

    int s = 0;
#pragma unroll 8
    for (int i = 0; i < 64; i++) s += (int)h[base + i];
    sm[t] = s;
    __syncthreads();
    for (int off = 1; off < 1024; off <<= 1) {
        int v = (t + off < 1024) ? sm[t + off] : 0;
        __syncthreads();
        sm[t] += v;
        __syncthreads();
    }

    if (sm[0] < TOPK) {
        if (t == 0) g_thr[b] = 0u;
        return;
    }
    bool found = (sm[t] >= TOPK) && (t == 1023 || sm[t + 1] < TOPK);
    if (found) {
        int acc = (t < 1023) ? sm[t + 1] : 0;
        int B = base;
        for (int i = 63; i >= 0; i--) {
            acc += (int)h[base + i];
            if (acc >= TOPK) { B = base + i; break; }
        }
        g_thr[b] = ((unsigned)B) << 16;
    }
}

// ---------------- K3: compact (warp-aggregated atomics) -------------------
__global__ void k_compact(const int* __restrict__ bidx, int N) {
    int p = blockIdx.x * 256 + threadIdx.x;
    unsigned long long key = 0ull;
    int b = -1;
    bool pred = false;
    if (p < N) {
        key = g_keyarr[p];
        b = bidx[p];
        pred = ((unsigned)(key >> 32) >= g_thr[b]);
    }
    const unsigned lane = threadIdx.x & 31;
#pragma unroll
    for (int bb = 0; bb < NUMB; bb++) {
        unsigned m = __ballot_sync(0xffffffffu, pred && (b == bb));
        if (m) {
            int leader = __ffs(m) - 1;
            int base = 0;
            if ((int)lane == leader) base = atomicAdd(&g_ccnt[bb], __popc(m));
            base = __shfl_sync(0xffffffffu, base, leader);
            if (pred && (b == bb)) {
                int slot = base + __popc(m & ((1u << lane) - 1u));
                if (slot < CAND) g_cand[bb][slot] = key;
            }
        }
    }
}

// ---------------- K4: PRECISE rescore of candidates -----------------------
__global__ void __launch_bounds__(128) k_rescore(
        const float* __restrict__ feat,
        const float* __restrict__ Wc,
        const float* __restrict__ bc,
        const float* __restrict__ Wr,
        const float* __restrict__ br,
        int N) {
    __shared__ float swc0[256], swc1[256], sw8[256];
    for (int i = threadIdx.x; i < 256; i += 128) {
        swc0[i] = Wc[2 * i + 0];
        swc1[i] = Wc[2 * i + 1];
        sw8[i]  = Wr[9 * i + 8];
    }
    __syncthreads();

    const int b = blockIdx.y;
    const int warp = threadIdx.x >> 5;
    const int lane = threadIdx.x & 31;
    const int k = blockIdx.x * 4 + warp;

    unsigned long long key = g_cand[b][k];
    unsigned idx = ~(unsigned)(key & 0xffffffffu);
    bool valid = (idx < (unsigned)N);

    double d0 = 0.0, d1 = 0.0, d2 = 0.0;
    if (valid) {
        const float4* f4 = (const float4*)(feat + (size_t)idx * 256);
        float4 a  = f4[lane * 2 + 0];
        float4 c4 = f4[lane * 2 + 1];
        float fv[8] = {a.x, a.y, a.z, a.w, c4.x, c4.y, c4.z, c4.w};
        const float* wp[3] = {&swc0[lane * 8], &swc1[lane * 8], &sw8[lane * 8]};
        double* dp[3] = {&d0, &d1, &d2};
#pragma unroll
        for (int o = 0; o < 3; o++) {
            float s = 0.0f, comp = 0.0f;
#pragma unroll
            for (int c = 0; c < 8; c++) {
                float v = fv[c], w = wp[o][c];
                float p = __fmul_rn(v, w);
                float e = __fmaf_rn(v, w, -p);      // exact product tail
                float t = __fadd_rn(s, p);          // Knuth TwoSum
                float bv = __fadd_rn(t, -s);
                float c1 = __fadd_rn(s, -__fadd_rn(t, -bv));
                float c2 = __fadd_rn(p, -bv);
                comp = __fadd_rn(comp, __fadd_rn(c1, c2));
                comp = __fadd_rn(comp, e);
                s = t;
            }
            *dp[o] = (double)s + (double)comp;
        }
    }
#pragma unroll
    for (int o = 16; o > 0; o >>= 1) {
        d0 += __shfl_xor_sync(0xffffffffu, d0, o);
        d1 += __shfl_xor_sync(0xffffffffu, d1, o);
        d2 += __shfl_xor_sync(0xffffffffu, d2, o);
    }

    if (lane == 0) {
        unsigned long long outk = 0ull;
        if (valid) {
            double l0 = d0 + (double)bc[0];
            double l1 = d1 + (double)bc[1];
            double r8 = d2 + (double)br[8];
            double m  = fmax(l0, l1);
            double e0 = exp(l0 - m);
            double e1 = exp(l1 - m);
            double conf = e1 / (e0 + e1);
            double scr  = 1.0 / (1.0 + exp(-r8));
            float sf = (float)(conf * scr);
            outk = ((unsigned long long)__float_as_uint(sf) << 32) |
                   (unsigned)(key & 0xffffffffu);
        }
        g_prec[b][k] = outk;
    }
}

// ---------------- K5a: sort each 1024-chunk descending (16 blocks) --------
__global__ void k_rank_leaf() {
    const int b = blockIdx.y;
    const int c = blockIdx.x;
    const int t = threadIdx.x;
    __shared__ unsigned long long s[1024];
    s[t] = g_prec[b][c * 1024 + t];

    for (unsigned k = 2; k <= 1024; k <<= 1) {
        for (unsigned jj = k >> 1; jj > 0; jj >>= 1) {
            __syncthreads();
            unsigned ixj = t ^ jj;
            if (ixj > (unsigned)t) {
                unsigned long long a = s[t], bb = s[ixj];
                bool desc = ((t & k) == 0);
                if (desc ? (a < bb) : (a > bb)) { s[t] = bb; s[ixj] = a; }
            }
        }
    }
    __syncthreads();
    g_prec[b][c * 1024 + t] = s[t];
}

// ---------------- K5b: merge chunk pairs -> top 1024 each (8 blocks) ------
__global__ void k_rank_m1() {
    const int b = blockIdx.y;
    const int c = blockIdx.x;      // 0..1
    const int t = threadIdx.x;
    __shared__ unsigned long long s[2048];
    s[t]        = g_prec[b][(2 * c) * 1024 + t];
    s[2047 - t] = g_prec[b][(2 * c + 1) * 1024 + t];
    for (unsigned jj = 1024; jj > 0; jj >>= 1) {
        __syncthreads();
#pragma unroll
        for (int rr = 0; rr < 2; rr++) {
            unsigned tt = t + rr * 1024;
            unsigned ixj = tt ^ jj;
            if (ixj > tt) {
                unsigned long long a = s[tt], bb = s[ixj];
                if (a < bb) { s[tt] = bb; s[ixj] = a; }
            }
        }
    }
    __syncthreads();
    g_tmp[b][c * 1024 + t] = s[t];
}

// ---------------- K5c: final merge -> sorted top 1024 (4 blocks) ----------
__global__ void k_rank_m2() {
    const int b = blockIdx.x;
    const int t = threadIdx.x;
    __shared__ unsigned long long s[2048];
    s[t]        = g_tmp[b][t];
    s[2047 - t] = g_tmp[b][1024 + t];
    for (unsigned jj = 1024; jj > 0; jj >>= 1) {
        __syncthreads();
#pragma unroll
        for (int rr = 0; rr < 2; rr++) {
            unsigned tt = t + rr * 1024;
            unsigned ixj = tt ^ jj;
            if (ixj > tt) {
                unsigned long long a = s[tt], bb = s[ixj];
                if (a < bb) { s[tt] = bb; s[ixj] = a; }
            }
        }
    }
    __syncthreads();
    g_sel[b][t] = s[t];
}

// ---------------- K6: decode boxes for selected 4096 points --------------
__global__ void __launch_bounds__(128) k_decode(
        const float* __restrict__ feat,
        const int*   __restrict__ coor,
        const float* __restrict__ Wr,
        const float* __restrict__ br,
        int N) {
    __shared__ float sW[256 * 9];
    __shared__ float srow[4][256];
    for (int i = threadIdx.x; i < 256 * 9; i += 128) sW[i] = Wr[i];
    __syncthreads();

    const int b = blockIdx.y;
    const int warp = threadIdx.x >> 5;
    const int lane = threadIdx.x & 31;
    const int k = blockIdx.x * 4 + warp;

    unsigned long long key = g_sel[b][k];
    unsigned idx = ~(unsigned)(key & 0xffffffffu);
    bool valid = (idx < (unsigned)N);
    if (!valid) idx = 0;

    {
        const float4* f4 = (const float4*)(feat + (size_t)idx * 256);
        float4 a = f4[lane * 2 + 0];
        float4 c4 = f4[lane * 2 + 1];
        ((float4*)srow[warp])[lane * 2 + 0] = a;
        ((float4*)srow[warp])[lane * 2 + 1] = c4;
    }
    __syncwarp();

    float acc = 0.0f;
    if (lane < 8) {
        const float* row = srow[warp];
#pragma unroll 8
        for (int kk = 0; kk < 256; kk++) {
            acc = __fmaf_rn(row[kk], sW[kk * 9 + lane], acc);
        }
        acc = __fadd_rn(acc, br[lane]);
    }

    float r[8];
#pragma unroll
    for (int j = 0; j < 8; j++) r[j] = __shfl_sync(0xffffffffu, acc, j);

    if (lane == 0) {
        float out[8];
        if (valid) {
            float cx = __fmul_rn((float)coor[(size_t)idx * 2 + 0], 0.8f);
            float cy = __fmul_rn((float)coor[(size_t)idx * 2 + 1], 0.8f);
            out[0] = __fadd_rn(cx, r[0]);
            out[1] = __fadd_rn(cy, r[1]);
            out[2] = r[2];
            out[3] = exp_cr(fminf(fmaxf(r[3], -6.0f), 6.0f));
            out[4] = exp_cr(fminf(fmaxf(r[4], -6.0f), 6.0f));
            out[5] = exp_cr(fminf(fmaxf(r[5], -6.0f), 6.0f));
            out[6] = atan2_cr(r[6], r[7]);
            out[7] = __uint_as_float((unsigned)(key >> 32));
        } else {
#pragma unroll
            for (int j = 0; j < 8; j++) out[j] = 0.0f;
        }
#pragma unroll
        for (int j = 0; j < 8; j++) g_boxes[b][k][j] = out[j];
    }
}

// ---------------- K7: IoU suppression bitmask (parallel) ------------------
__global__ void k_mask() {
    const int b = blockIdx.y;
    const int j = threadIdx.x;                 // column
    __shared__ float sx1[PRE], sx2[PRE], sy1[PRE], sy2[PRE], sa[PRE];

    float x = g_boxes[b][j][0], y = g_boxes[b][j][1];
    float l = g_boxes[b][j][3], w = g_boxes[b][j][4];
    bool jv = (~(unsigned)(g_sel[b][j] & 0xffffffffu)) < 0x7fffffffu;
    if (jv) {
        float lh = __fmul_rn(l, 0.5f);
        float wh = __fmul_rn(w, 0.5f);
        sx1[j] = __fadd_rn(x, -lh); sx2[j] = __fadd_rn(x, lh);
        sy1[j] = __fadd_rn(y, -wh); sy2[j] = __fadd_rn(y, wh);
        sa[j]  = __fmul_rn(l, w);
    } else {
        sx1[j] = 1e30f; sx2[j] = -1e30f;
        sy1[j] = 1e30f; sy2[j] = -1e30f;
        sa[j]  = 0.0f;
    }
    __syncthreads();

    const int i0 = blockIdx.x * 32;
    const float X1 = sx1[j], X2 = sx2[j], Y1 = sy1[j], Y2 = sy2[j], A = sa[j];
    for (int ii = 0; ii < 32; ii++) {
        int i = i0 + ii;
        float ix = fmaxf(__fadd_rn(fminf(sx2[i], X2), -fmaxf(sx1[i], X1)), 0.0f);
        float iy = fmaxf(__fadd_rn(fminf(sy2[i], Y2), -fmaxf(sy1[i], Y1)), 0.0f);
        float inter = __fmul_rn(ix, iy);
        float uni = __fadd_rn(__fadd_rn(sa[i], A), -inter);
        float iou = __fdiv_rn(inter, fmaxf(uni, 1e-6f));
        bool s = (j > i) && (iou > 0.1f);
        unsigned bal = __ballot_sync(0xffffffffu, s);
        if ((j & 31) == 0) {
            g_mask[b][i][j >> 5] = bal;
            if (bal) atomicOr(&g_rowflag[b][i >> 5], 1u << (i & 31));
        }
    }
}

// ---------------- K8: serial greedy scan (sparse rows only) + outputs -----
__global__ void k_scan_out(float* __restrict__ dout, int out_size) {
    const int b = blockIdx.x;
    const int t = threadIdx.x;
    __shared__ unsigned srem[32];

    if (t < 32) {
        unsigned rem = 0;
        unsigned flags = g_rowflag[b][t];
        for (int w = 0; w < 32; w++) {
            unsigned fw = __shfl_sync(0xffffffffu, flags, w);
            while (fw) {
                int bp = __ffs(fw) - 1;
                fw &= fw - 1;
                int i = w * 32 + bp;
                unsigned owner = __shfl_sync(0xffffffffu, rem, i >> 5);
                if (!((owner >> (i & 31)) & 1u)) {
                    rem |= g_mask[b][i][t];
                }
            }
        }
        srem[t] = rem;
    }
    __syncthreads();

    bool jv = (~(unsigned)(g_sel[b][t] & 0xffffffffu)) < 0x7fffffffu;
    bool keep = jv && !((srem[t >> 5] >> (t & 31)) & 1u);
    float kf = keep ? 1.0f : 0.0f;

    int obase = (b * PRE + t) * 8;
#pragma unroll
    for (int c = 0; c < 8; c++) {
        if (obase + c < out_size) dout[obase + c] = g_boxes[b][t][c] * kf;
    }
    int lbpos = NUMB * PRE * 8 + b * PRE + t;          // label section (always 0)
    if (lbpos < out_size) dout[lbpos] = 0.0f;
    int kppos = NUMB * PRE * 9 + b * PRE + t;          // keep section
    if (kppos < out_size) dout[kppos] = kf;
}

// ---------------- launcher ----------------
extern "C" void kernel_launch(void* const* d_in, const int* in_sizes, int n_in,
                              void* d_out, int out_size) {
    const float* feat  = (const float*)d_in[0];
    const int*   bidx  = (const int*)d_in[1];
    const int*   coor  = (const int*)d_in[2];
    const float* Wc    = (const float*)d_in[3];
    const float* bc    = (const float*)d_in[4];
    const float* Wr    = (const float*)d_in[5];
    const float* br    = (const float*)d_in[6];
    float* out = (float*)d_out;

    const int N = in_sizes[1];

    k_zero_hist<<<256, 256>>>();                 // launch 1
    k_zero_cand<<<32, 256>>>();                  // launch 2
    k_zero_misc<<<1, 256>>>();                   // launch 3
    k_score<<<(N + 255) / 256, 256>>>(feat, bidx, Wc, bc, Wr, br, N);  // launch 4 (profiled)
    k_thresh<<<NUMB, 1024>>>();
    k_compact<<<(N + 255) / 256, 256>>>(bidx, N);
    k_rescore<<<dim3(CAND / 4, NUMB), 128>>>(feat, Wc, bc, Wr, br, N);
    k_rank_leaf<<<dim3(4, NUMB), 1024>>>();
    k_rank_m1<<<dim3(2, NUMB), 1024>>>();
    k_rank_m2<<<NUMB, 1024>>>();
    k_decode<<<dim3(PRE / 4, NUMB), 128>>>(feat, coor, Wr, br, N);
    k_mask<<<dim3(PRE / 32, NUMB), 1024>>>();
    k_scan_out<<<NUMB, 1024>>>(out, out_size);
}

// round 9
// speedup vs baseline: 1.3855x; 1.1658x over previous
#include <cuda_runtime.h>
#include <cstdint>
#include <math.h>

#define NUMB   4
#define PRE    1024
#define CAND   4096
#define HBINS  65536
#define MAXN   200000
#define TOPK   2048

// ---------------- device scratch (static, no runtime alloc) ----------------
__device__ unsigned long long g_keyarr[MAXN];
__device__ unsigned           g_hist[NUMB][HBINS];
__device__ unsigned           g_part[NUMB][32];
__device__ unsigned           g_thr[NUMB];
__device__ int                g_ccnt[NUMB];
__device__ unsigned long long g_cand[NUMB][CAND];
__device__ unsigned long long g_prec[NUMB][CAND];
__device__ unsigned long long g_tmp[NUMB][2048];
__device__ unsigned long long g_sel[NUMB][PRE];
__device__ float              g_boxes[NUMB][PRE][8];
__device__ unsigned           g_mask[NUMB][PRE][32];
__device__ unsigned           g_rowflag[NUMB][32];

__device__ __forceinline__ float exp_cr(float x)  { return (float)exp((double)x); }
__device__ __forceinline__ float atan2_cr(float y, float x) {
    return (float)atan2((double)y, (double)x);
}

// ---------------- K0: one zero kernel for everything ----------------------
// uint4 slots: hist = 65536, cand = 8192, then misc tail.
__global__ void k_zero_all() {
    int i = blockIdx.x * 256 + threadIdx.x;
    if (i < HBINS) {                           // 65536 uint4 = whole hist
        ((uint4*)g_hist)[i] = make_uint4(0, 0, 0, 0);
    } else if (i < HBINS + NUMB * CAND / 2) {  // 8192 uint4 = whole cand
        ((uint4*)g_cand)[i - HBINS] = make_uint4(0, 0, 0, 0);
    } else {
        int t = i - (HBINS + NUMB * CAND / 2);
        if (t < NUMB) g_ccnt[t] = 0;
        if (t < NUMB * 32) ((unsigned*)g_rowflag)[t] = 0;
    }
}

// ---------------- K1: APPROX score pass + histogram (prefetch-pipelined) --
__global__ void __launch_bounds__(256) k_score(
        const float* __restrict__ feat,
        const int*   __restrict__ bidx,
        const float* __restrict__ Wc,
        const float* __restrict__ bc,
        const float* __restrict__ Wr,
        const float* __restrict__ br,
        int N) {
    const int warp = threadIdx.x >> 5;
    const int lane = threadIdx.x & 31;
    const int j    = lane & 15;        // lane within point
    const int sub  = lane >> 4;        // which of the 2 points

    float wd[4][4], w8[4][4];
#pragma unroll
    for (int q = 0; q < 4; q++) {
#pragma unroll
        for (int e = 0; e < 4; e++) {
            int f = 4 * (j + 16 * q) + e;
            wd[q][e] = Wc[f * 2 + 1] - Wc[f * 2 + 0];
            w8[q][e] = Wr[f * 9 + 8];
        }
    }
    const float bd  = bc[1] - bc[0];
    const float b8r = br[8];

    const int base0 = blockIdx.x * 256 + warp * 32;

    float4 c0, c1, c2, c3;
    {
        int p = base0 + sub;
        if (p < N) {
            const float4* f4 = (const float4*)(feat + (size_t)p * 256);
            c0 = f4[j]; c1 = f4[j + 16]; c2 = f4[j + 32]; c3 = f4[j + 48];
        } else {
            c0 = c1 = c2 = c3 = make_float4(0.f, 0.f, 0.f, 0.f);
        }
    }

    for (int it = 0; it < 16; it++) {
        float4 n0, n1, n2, n3;
        int pn = base0 + (it + 1) * 2 + sub;
        if (it < 15 && pn < N) {
            const float4* f4n = (const float4*)(feat + (size_t)pn * 256);
            n0 = f4n[j]; n1 = f4n[j + 16]; n2 = f4n[j + 32]; n3 = f4n[j + 48];
        } else {
            n0 = n1 = n2 = n3 = make_float4(0.f, 0.f, 0.f, 0.f);
        }

        float d0 = c0.x * wd[0][0] + c0.y * wd[0][1] + c0.z * wd[0][2] + c0.w * wd[0][3];
        float d1 = c1.x * wd[1][0] + c1.y * wd[1][1] + c1.z * wd[1][2] + c1.w * wd[1][3];
        float d2 = c2.x * wd[2][0] + c2.y * wd[2][1] + c2.z * wd[2][2] + c2.w * wd[2][3];
        float d3 = c3.x * wd[3][0] + c3.y * wd[3][1] + c3.z * wd[3][2] + c3.w * wd[3][3];
        float accd = (d0 + d1) + (d2 + d3);
        float r0 = c0.x * w8[0][0] + c0.y * w8[0][1] + c0.z * w8[0][2] + c0.w * w8[0][3];
        float r1 = c1.x * w8[1][0] + c1.y * w8[1][1] + c1.z * w8[1][2] + c1.w * w8[1][3];
        float r2 = c2.x * w8[2][0] + c2.y * w8[2][1] + c2.z * w8[2][2] + c2.w * w8[2][3];
        float r3 = c3.x * w8[3][0] + c3.y * w8[3][1] + c3.z * w8[3][2] + c3.w * w8[3][3];
        float accr = (r0 + r1) + (r2 + r3);

#pragma unroll
        for (int o = 8; o > 0; o >>= 1) {
            accd += __shfl_xor_sync(0xffffffffu, accd, o);
            accr += __shfl_xor_sync(0xffffffffu, accr, o);
        }
        int p_cur = base0 + it * 2 + sub;
        if (j == 0 && p_cur < N) {
            float s = 1.0f / ((1.0f + expf(-(accd + bd))) * (1.0f + expf(-(accr + b8r))));
            unsigned sb = __float_as_uint(s);
            g_keyarr[p_cur] = ((unsigned long long)sb << 32) | (unsigned)(~(unsigned)p_cur);
            atomicAdd(&g_hist[bidx[p_cur]][sb >> 16], 1u);
        }
        c0 = n0; c1 = n1; c2 = n2; c3 = n3;
    }
}

// ---------------- K2a: partial bin sums (coalesced, 128 blocks) -----------
// block (r, b): sums bins [r*2048, (r+1)*2048) of batch b.
__global__ void k_part() {
    const int b = blockIdx.y;
    const int r = blockIdx.x;
    const int t = threadIdx.x;
    __shared__ int sm[256];
    const uint4* h4 = (const uint4*)&g_hist[b][r * 2048];   // 512 uint4
    uint4 a = h4[t];
    uint4 c = h4[t + 256];
    sm[t] = (int)(a.x + a.y + a.z + a.w + c.x + c.y + c.z + c.w);
    __syncthreads();
    for (int off = 128; off > 0; off >>= 1) {
        if (t < off) sm[t] += sm[t + off];
        __syncthreads();
    }
    if (t == 0) g_part[b][r] = (unsigned)sm[0];
}

// ---------------- K2b: exact threshold (coarse suffix + fine scan) --------
__global__ void k_thresh2() {
    const int b = blockIdx.x;
    const int t = threadIdx.x;
    __shared__ unsigned spart[32];
    __shared__ unsigned ssuf[33];
    __shared__ int s_range;
    __shared__ unsigned s_tail;
    __shared__ unsigned tsum[256];

    if (t < 32) spart[t] = g_part[b][t];
    __syncthreads();
    if (t == 0) {
        unsigned acc = 0;
        ssuf[32] = 0;
        for (int r = 31; r >= 0; r--) { acc += spart[r]; ssuf[r] = acc; }
        if (ssuf[0] < TOPK) {
            s_range = -1;
            g_thr[b] = 0u;
        } else {
            int rr = 31;
            while (ssuf[rr] < TOPK) rr--;   // largest r with suffix >= TOPK
            s_range = rr;
            s_tail = ssuf[rr + 1];
        }
    }
    __syncthreads();
    int range = s_range;
    if (range < 0) return;

    // fine scan over bins [range*2048, range*2048+2048)
    const unsigned* h = &g_hist[b][range * 2048];
    unsigned v[8];
    const uint4* h4 = (const uint4*)h;
    uint4 a = h4[t * 2], c = h4[t * 2 + 1];
    v[0] = a.x; v[1] = a.y; v[2] = a.z; v[3] = a.w;
    v[4] = c.x; v[5] = c.y; v[6] = c.z; v[7] = c.w;
    unsigned mysum = v[0] + v[1] + v[2] + v[3] + v[4] + v[5] + v[6] + v[7];
    tsum[t] = mysum;
    __syncthreads();
    // exclusive suffix over thread sums: S_t = sum_{t' > t} tsum[t']
    // simple smem suffix scan
    for (int off = 1; off < 256; off <<= 1) {
        unsigned add = (t + off < 256) ? tsum[t + off] : 0;
        __syncthreads();
        tsum[t] += add;
        __syncthreads();
    }
    unsigned S_t = ((t + 1 < 256) ? tsum[t + 1] : 0) + s_tail;
    // walk own 8 bins from high to low; unique global crossing of TOPK
    unsigned acc = S_t;
    int Bbin = -1;
    for (int i = 7; i >= 0; i--) {
        acc += v[i];
        if (acc >= TOPK) { Bbin = t * 8 + i; break; }
    }
    if (Bbin >= 0 && (acc - v[Bbin & 7] < TOPK || true)) {
        // the crossing thread is the one whose final acc first reached TOPK
        // uniqueness: crossing bin is unique; only the thread owning it breaks
        // with acc >= TOPK while its S_t < TOPK.
        if (S_t < TOPK) {
            g_thr[b] = ((unsigned)(range * 2048 + Bbin)) << 16;
        }
    }
}

// ---------------- K3: compact (warp-aggregated atomics) -------------------
__global__ void k_compact(const int* __restrict__ bidx, int N) {
    int p = blockIdx.x * 256 + threadIdx.x;
    unsigned long long key = 0ull;
    int b = -1;
    bool pred = false;
    if (p < N) {
        key = g_keyarr[p];
        b = bidx[p];
        pred = ((unsigned)(key >> 32) >= g_thr[b]);
    }
    const unsigned lane = threadIdx.x & 31;
#pragma unroll
    for (int bb = 0; bb < NUMB; bb++) {
        unsigned m = __ballot_sync(0xffffffffu, pred && (b == bb));
        if (m) {
            int leader = __ffs(m) - 1;
            int base = 0;
            if ((int)lane == leader) base = atomicAdd(&g_ccnt[bb], __popc(m));
            base = __shfl_sync(0xffffffffu, base, leader);
            if (pred && (b == bb)) {
                int slot = base + __popc(m & ((1u << lane) - 1u));
                if (slot < CAND) g_cand[bb][slot] = key;
            }
        }
    }
}

// ---------------- K4: PRECISE rescore of candidates -----------------------
__global__ void __launch_bounds__(128) k_rescore(
        const float* __restrict__ feat,
        const float* __restrict__ Wc,
        const float* __restrict__ bc,
        const float* __restrict__ Wr,
        const float* __restrict__ br,
        int N) {
    __shared__ float swc0[256], swc1[256], sw8[256];
    for (int i = threadIdx.x; i < 256; i += 128) {
        swc0[i] = Wc[2 * i + 0];
        swc1[i] = Wc[2 * i + 1];
        sw8[i]  = Wr[9 * i + 8];
    }
    __syncthreads();

    const int b = blockIdx.y;
    const int warp = threadIdx.x >> 5;
    const int lane = threadIdx.x & 31;
    const int k = blockIdx.x * 4 + warp;

    unsigned long long key = g_cand[b][k];
    unsigned idx = ~(unsigned)(key & 0xffffffffu);
    bool valid = (idx < (unsigned)N);

    double d0 = 0.0, d1 = 0.0, d2 = 0.0;
    if (valid) {
        const float4* f4 = (const float4*)(feat + (size_t)idx * 256);
        float4 a  = f4[lane * 2 + 0];
        float4 c4 = f4[lane * 2 + 1];
        float fv[8] = {a.x, a.y, a.z, a.w, c4.x, c4.y, c4.z, c4.w};
        const float* wp[3] = {&swc0[lane * 8], &swc1[lane * 8], &sw8[lane * 8]};
        double* dp[3] = {&d0, &d1, &d2};
#pragma unroll
        for (int o = 0; o < 3; o++) {
            float s = 0.0f, comp = 0.0f;
#pragma unroll
            for (int c = 0; c < 8; c++) {
                float v = fv[c], w = wp[o][c];
                float p = __fmul_rn(v, w);
                float e = __fmaf_rn(v, w, -p);
                float t = __fadd_rn(s, p);
                float bv = __fadd_rn(t, -s);
                float c1 = __fadd_rn(s, -__fadd_rn(t, -bv));
                float c2 = __fadd_rn(p, -bv);
                comp = __fadd_rn(comp, __fadd_rn(c1, c2));
                comp = __fadd_rn(comp, e);
                s = t;
            }
            *dp[o] = (double)s + (double)comp;
        }
    }
#pragma unroll
    for (int o = 16; o > 0; o >>= 1) {
        d0 += __shfl_xor_sync(0xffffffffu, d0, o);
        d1 += __shfl_xor_sync(0xffffffffu, d1, o);
        d2 += __shfl_xor_sync(0xffffffffu, d2, o);
    }

    if (lane == 0) {
        unsigned long long outk = 0ull;
        if (valid) {
            double l0 = d0 + (double)bc[0];
            double l1 = d1 + (double)bc[1];
            double r8 = d2 + (double)br[8];
            double m  = fmax(l0, l1);
            double e0 = exp(l0 - m);
            double e1 = exp(l1 - m);
            double conf = e1 / (e0 + e1);
            double scr  = 1.0 / (1.0 + exp(-r8));
            float sf = (float)(conf * scr);
            outk = ((unsigned long long)__float_as_uint(sf) << 32) |
                   (unsigned)(key & 0xffffffffu);
        }
        g_prec[b][k] = outk;
    }
}

// ---------------- K5a: sort each 1024-chunk descending (16 blocks) --------
__global__ void k_rank_leaf() {
    const int b = blockIdx.y;
    const int c = blockIdx.x;
    const int t = threadIdx.x;
    __shared__ unsigned long long s[1024];
    s[t] = g_prec[b][c * 1024 + t];

    for (unsigned k = 2; k <= 1024; k <<= 1) {
        for (unsigned jj = k >> 1; jj > 0; jj >>= 1) {
            __syncthreads();
            unsigned ixj = t ^ jj;
            if (ixj > (unsigned)t) {
                unsigned long long a = s[t], bb = s[ixj];
                bool desc = ((t & k) == 0);
                if (desc ? (a < bb) : (a > bb)) { s[t] = bb; s[ixj] = a; }
            }
        }
    }
    __syncthreads();
    g_prec[b][c * 1024 + t] = s[t];
}

// ---------------- K5b: merge chunk pairs -> top 1024 each (8 blocks) ------
__global__ void k_rank_m1() {
    const int b = blockIdx.y;
    const int c = blockIdx.x;
    const int t = threadIdx.x;
    __shared__ unsigned long long s[2048];
    s[t]        = g_prec[b][(2 * c) * 1024 + t];
    s[2047 - t] = g_prec[b][(2 * c + 1) * 1024 + t];
    for (unsigned jj = 1024; jj > 0; jj >>= 1) {
        __syncthreads();
#pragma unroll
        for (int rr = 0; rr < 2; rr++) {
            unsigned tt = t + rr * 1024;
            unsigned ixj = tt ^ jj;
            if (ixj > tt) {
                unsigned long long a = s[tt], bb = s[ixj];
                if (a < bb) { s[tt] = bb; s[ixj] = a; }
            }
        }
    }
    __syncthreads();
    g_tmp[b][c * 1024 + t] = s[t];
}

// ---------------- K5c: final merge -> sorted top 1024 (4 blocks) ----------
__global__ void k_rank_m2() {
    const int b = blockIdx.x;
    const int t = threadIdx.x;
    __shared__ unsigned long long s[2048];
    s[t]        = g_tmp[b][t];
    s[2047 - t] = g_tmp[b][1024 + t];
    for (unsigned jj = 1024; jj > 0; jj >>= 1) {
        __syncthreads();
#pragma unroll
        for (int rr = 0; rr < 2; rr++) {
            unsigned tt = t + rr * 1024;
            unsigned ixj = tt ^ jj;
            if (ixj > tt) {
                unsigned long long a = s[tt], bb = s[ixj];
                if (a < bb) { s[tt] = bb; s[ixj] = a; }
            }
        }
    }
    __syncthreads();
    g_sel[b][t] = s[t];
}

// ---------------- K6: decode boxes for selected 4096 points --------------
__global__ void __launch_bounds__(128) k_decode(
        const float* __restrict__ feat,
        const int*   __restrict__ coor,
        const float* __restrict__ Wr,
        const float* __restrict__ br,
        int N) {
    __shared__ float sW[256 * 9];
    __shared__ float srow[4][256];
    for (int i = threadIdx.x; i < 256 * 9; i += 128) sW[i] = Wr[i];
    __syncthreads();

    const int b = blockIdx.y;
    const int warp = threadIdx.x >> 5;
    const int lane = threadIdx.x & 31;
    const int k = blockIdx.x * 4 + warp;

    unsigned long long key = g_sel[b][k];
    unsigned idx = ~(unsigned)(key & 0xffffffffu);
    bool valid = (idx < (unsigned)N);
    if (!valid) idx = 0;

    {
        const float4* f4 = (const float4*)(feat + (size_t)idx * 256);
        float4 a = f4[lane * 2 + 0];
        float4 c4 = f4[lane * 2 + 1];
        ((float4*)srow[warp])[lane * 2 + 0] = a;
        ((float4*)srow[warp])[lane * 2 + 1] = c4;
    }
    __syncwarp();

    float acc = 0.0f;
    if (lane < 8) {
        const float* row = srow[warp];
#pragma unroll 8
        for (int kk = 0; kk < 256; kk++) {
            acc = __fmaf_rn(row[kk], sW[kk * 9 + lane], acc);
        }
        acc = __fadd_rn(acc, br[lane]);
    }

    float r[8];
#pragma unroll
    for (int j = 0; j < 8; j++) r[j] = __shfl_sync(0xffffffffu, acc, j);

    if (lane == 0) {
        float out[8];
        if (valid) {
            float cx = __fmul_rn((float)coor[(size_t)idx * 2 + 0], 0.8f);
            float cy = __fmul_rn((float)coor[(size_t)idx * 2 + 1], 0.8f);
            out[0] = __fadd_rn(cx, r[0]);
            out[1] = __fadd_rn(cy, r[1]);
            out[2] = r[2];
            out[3] = exp_cr(fminf(fmaxf(r[3], -6.0f), 6.0f));
            out[4] = exp_cr(fminf(fmaxf(r[4], -6.0f), 6.0f));
            out[5] = exp_cr(fminf(fmaxf(r[5], -6.0f), 6.0f));
            out[6] = atan2_cr(r[6], r[7]);
            out[7] = __uint_as_float((unsigned)(key >> 32));
        } else {
#pragma unroll
            for (int j = 0; j < 8; j++) out[j] = 0.0f;
        }
#pragma unroll
        for (int j = 0; j < 8; j++) g_boxes[b][k][j] = out[j];
    }
}

// ---------------- K7: IoU suppression bitmask (parallel) ------------------
__global__ void k_mask() {
    const int b = blockIdx.y;
    const int j = threadIdx.x;
    __shared__ float sx1[PRE], sx2[PRE], sy1[PRE], sy2[PRE], sa[PRE];

    float x = g_boxes[b][j][0], y = g_boxes[b][j][1];
    float l = g_boxes[b][j][3], w = g_boxes[b][j][4];
    bool jv = (~(unsigned)(g_sel[b][j] & 0xffffffffu)) < 0x7fffffffu;
    if (jv) {
        float lh = __fmul_rn(l, 0.5f);
        float wh = __fmul_rn(w, 0.5f);
        sx1[j] = __fadd_rn(x, -lh); sx2[j] = __fadd_rn(x, lh);
        sy1[j] = __fadd_rn(y, -wh); sy2[j] = __fadd_rn(y, wh);
        sa[j]  = __fmul_rn(l, w);
    } else {
        sx1[j] = 1e30f; sx2[j] = -1e30f;
        sy1[j] = 1e30f; sy2[j] = -1e30f;
        sa[j]  = 0.0f;
    }
    __syncthreads();

    const int i0 = blockIdx.x * 32;
    const float X1 = sx1[j], X2 = sx2[j], Y1 = sy1[j], Y2 = sy2[j], A = sa[j];
    for (int ii = 0; ii < 32; ii++) {
        int i = i0 + ii;
        float ix = fmaxf(__fadd_rn(fminf(sx2[i], X2), -fmaxf(sx1[i], X1)), 0.0f);
        float iy = fmaxf(__fadd_rn(fminf(sy2[i], Y2), -fmaxf(sy1[i], Y1)), 0.0f);
        float inter = __fmul_rn(ix, iy);
        float uni = __fadd_rn(__fadd_rn(sa[i], A), -inter);
        float iou = __fdiv_rn(inter, fmaxf(uni, 1e-6f));
        bool s = (j > i) && (iou > 0.1f);
        unsigned bal = __ballot_sync(0xffffffffu, s);
        if ((j & 31) == 0) {
            g_mask[b][i][j >> 5] = bal;
            if (bal) atomicOr(&g_rowflag[b][i >> 5], 1u << (i & 31));
        }
    }
}

// ---------------- K8: serial greedy scan (sparse rows only) + outputs -----
__global__ void k_scan_out(float* __restrict__ dout, int out_size) {
    const int b = blockIdx.x;
    const int t = threadIdx.x;
    __shared__ unsigned srem[32];

    if (t < 32) {
        unsigned rem = 0;
        unsigned flags = g_rowflag[b][t];
        for (int w = 0; w < 32; w++) {
            unsigned fw = __shfl_sync(0xffffffffu, flags, w);
            while (fw) {
                int bp = __ffs(fw) - 1;
                fw &= fw - 1;
                int i = w * 32 + bp;
                unsigned owner = __shfl_sync(0xffffffffu, rem, i >> 5);
                if (!((owner >> (i & 31)) & 1u)) {
                    rem |= g_mask[b][i][t];
                }
            }
        }
        srem[t] = rem;
    }
    __syncthreads();

    bool jv = (~(unsigned)(g_sel[b][t] & 0xffffffffu)) < 0x7fffffffu;
    bool keep = jv && !((srem[t >> 5] >> (t & 31)) & 1u);
    float kf = keep ? 1.0f : 0.0f;

    int obase = (b * PRE + t) * 8;
#pragma unroll
    for (int c = 0; c < 8; c++) {
        if (obase + c < out_size) dout[obase + c] = g_boxes[b][t][c] * kf;
    }
    int lbpos = NUMB * PRE * 8 + b * PRE + t;
    if (lbpos < out_size) dout[lbpos] = 0.0f;
    int kppos = NUMB * PRE * 9 + b * PRE + t;
    if (kppos < out_size) dout[kppos] = kf;
}

// ---------------- launcher ----------------
extern "C" void kernel_launch(void* const* d_in, const int* in_sizes, int n_in,
                              void* d_out, int out_size) {
    const float* feat  = (const float*)d_in[0];
    const int*   bidx  = (const int*)d_in[1];
    const int*   coor  = (const int*)d_in[2];
    const float* Wc    = (const float*)d_in[3];
    const float* bc    = (const float*)d_in[4];
    const float* Wr    = (const float*)d_in[5];
    const float* br    = (const float*)d_in[6];
    float* out = (float*)d_out;

    const int N = in_sizes[1];

    k_zero_all<<<(HBINS + NUMB * CAND / 2 + NUMB * 33 + 255) / 256, 256>>>();
    k_score<<<(N + 255) / 256, 256>>>(feat, bidx, Wc, bc, Wr, br, N);
    k_part<<<dim3(32, NUMB), 256>>>();
    k_thresh2<<<NUMB, 256>>>();
    k_compact<<<(N + 255) / 256, 256>>>(bidx, N);
    k_rescore<<<dim3(CAND / 4, NUMB), 128>>>(feat, Wc, bc, Wr, br, N);
    k_rank_leaf<<<dim3(4, NUMB), 1024>>>();
    k_rank_m1<<<dim3(2, NUMB), 1024>>>();
    k_rank_m2<<<NUMB, 1024>>>();
    k_decode<<<dim3(PRE / 4, NUMB), 128>>>(feat, coor, Wr, br, N);
    k_mask<<<dim3(PRE / 32, NUMB), 1024>>>();
    k_scan_out<<<NUMB, 1024>>>(out, out_size);
}

// round 12
// speedup vs baseline: 1.5217x; 1.0983x over previous
#include <cuda_runtime.h>
#include <cstdint>
#include <math.h>

#define NUMB   4
#define PRE    1024
#define CAND   4096
#define HBINS  65536
#define MAXN   200000
#define TOPK   2048

// ---------------- device scratch (static, no runtime alloc) ----------------
__device__ unsigned long long g_keyarr[MAXN];
__device__ unsigned           g_hist[NUMB][HBINS];
__device__ unsigned           g_thr[NUMB];
__device__ int                g_ccnt[NUMB];
__device__ unsigned long long g_cand[NUMB][CAND];
__device__ unsigned long long g_prec[NUMB][CAND];
__device__ float              g_regs[NUMB][CAND][8];
__device__ unsigned long long g_tmp[NUMB][2048];
__device__ unsigned long long g_sel[NUMB][PRE];
__device__ float              g_boxes[NUMB][PRE][8];
__device__ unsigned           g_mask[NUMB][PRE][32];
__device__ unsigned           g_rowflag[NUMB][32];

// ---------------- K0: zero hist / cand / counters / flags ----------------
__global__ void k_zero_all() {
    int i = blockIdx.x * 256 + threadIdx.x;
    if (i < HBINS) {                           // 65536 uint4 = whole hist
        ((uint4*)g_hist)[i] = make_uint4(0, 0, 0, 0);
    } else if (i < HBINS + NUMB * CAND / 2) {  // 8192 uint4 = whole cand
        ((uint4*)g_cand)[i - HBINS] = make_uint4(0, 0, 0, 0);
    } else {
        int t = i - (HBINS + NUMB * CAND / 2);
        if (t < NUMB) g_ccnt[t] = 0;
        if (t < NUMB * 32) ((unsigned*)g_rowflag)[t] = 0;
    }
}

// ---------------- K1: APPROX score pass + histogram (prefetch-pipelined) --
__global__ void __launch_bounds__(256) k_score(
        const float* __restrict__ feat,
        const int*   __restrict__ bidx,
        const float* __restrict__ Wc,
        const float* __restrict__ bc,
        const float* __restrict__ Wr,
        const float* __restrict__ br,
        int N) {
    const int warp = threadIdx.x >> 5;
    const int lane = threadIdx.x & 31;
    const int j    = lane & 15;        // lane within point
    const int sub  = lane >> 4;        // which of the 2 points

    float wd[4][4], w8[4][4];
#pragma unroll
    for (int q = 0; q < 4; q++) {
#pragma unroll
        for (int e = 0; e < 4; e++) {
            int f = 4 * (j + 16 * q) + e;
            wd[q][e] = Wc[f * 2 + 1] - Wc[f * 2 + 0];
            w8[q][e] = Wr[f * 9 + 8];
        }
    }
    const float bd  = bc[1] - bc[0];
    const float b8r = br[8];

    const int base0 = blockIdx.x * 256 + warp * 32;

    float4 c0, c1, c2, c3;
    {
        int p = base0 + sub;
        if (p < N) {
            const float4* f4 = (const float4*)(feat + (size_t)p * 256);
            c0 = f4[j]; c1 = f4[j + 16]; c2 = f4[j + 32]; c3 = f4[j + 48];
        } else {
            c0 = c1 = c2 = c3 = make_float4(0.f, 0.f, 0.f, 0.f);
        }
    }

    for (int it = 0; it < 16; it++) {
        float4 n0, n1, n2, n3;
        int pn = base0 + (it + 1) * 2 + sub;
        if (it < 15 && pn < N) {
            const float4* f4n = (const float4*)(feat + (size_t)pn * 256);
            n0 = f4n[j]; n1 = f4n[j + 16]; n2 = f4n[j + 32]; n3 = f4n[j + 48];
        } else {
            n0 = n1 = n2 = n3 = make_float4(0.f, 0.f, 0.f, 0.f);
        }

        float d0 = c0.x * wd[0][0] + c0.y * wd[0][1] + c0.z * wd[0][2] + c0.w * wd[0][3];
        float d1 = c1.x * wd[1][0] + c1.y * wd[1][1] + c1.z * wd[1][2] + c1.w * wd[1][3];
        float d2 = c2.x * wd[2][0] + c2.y * wd[2][1] + c2.z * wd[2][2] + c2.w * wd[2][3];
        float d3 = c3.x * wd[3][0] + c3.y * wd[3][1] + c3.z * wd[3][2] + c3.w * wd[3][3];
        float accd = (d0 + d1) + (d2 + d3);
        float r0 = c0.x * w8[0][0] + c0.y * w8[0][1] + c0.z * w8[0][2] + c0.w * w8[0][3];
        float r1 = c1.x * w8[1][0] + c1.y * w8[1][1] + c1.z * w8[1][2] + c1.w * w8[1][3];
        float r2 = c2.x * w8[2][0] + c2.y * w8[2][1] + c2.z * w8[2][2] + c2.w * w8[2][3];
        float r3 = c3.x * w8[3][0] + c3.y * w8[3][1] + c3.z * w8[3][2] + c3.w * w8[3][3];
        float accr = (r0 + r1) + (r2 + r3);

#pragma unroll
        for (int o = 8; o > 0; o >>= 1) {
            accd += __shfl_xor_sync(0xffffffffu, accd, o);
            accr += __shfl_xor_sync(0xffffffffu, accr, o);
        }
        int p_cur = base0 + it * 2 + sub;
        if (j == 0 && p_cur < N) {
            float s = 1.0f / ((1.0f + expf(-(accd + bd))) * (1.0f + expf(-(accr + b8r))));
            unsigned sb = __float_as_uint(s);
            g_keyarr[p_cur] = ((unsigned long long)sb << 32) | (unsigned)(~(unsigned)p_cur);
            atomicAdd(&g_hist[bidx[p_cur]][sb >> 16], 1u);
        }
        c0 = n0; c1 = n1; c2 = n2; c3 = n3;
    }
}

// ---------------- K2: fused threshold (4 blocks x 1024 threads) -----------
__global__ void __launch_bounds__(1024) k_thresh() {
    const int b = blockIdx.x;
    const int t = threadIdx.x;
    __shared__ unsigned tsum[1024];

    // per-thread: 64 contiguous bins via 16 uint4 (kept in registers)
    const uint4* h4 = (const uint4*)&g_hist[b][0];
    uint4 v4[16];
    unsigned mysum = 0;
#pragma unroll
    for (int i = 0; i < 16; i++) {
        v4[i] = h4[t * 16 + i];
        mysum += v4[i].x + v4[i].y + v4[i].z + v4[i].w;
    }
    tsum[t] = mysum;
    __syncthreads();
    // inclusive suffix scan over thread sums
    for (int off = 1; off < 1024; off <<= 1) {
        unsigned add = (t + off < 1024) ? tsum[t + off] : 0;
        __syncthreads();
        tsum[t] += add;
        __syncthreads();
    }
    unsigned total = tsum[0];
    unsigned S = (t < 1023) ? tsum[t + 1] : 0;
    if (t == 0 && total < TOPK) g_thr[b] = 0u;
    if (total >= TOPK && S < TOPK && S + mysum >= TOPK) {
        unsigned acc = S;
        int bin = -1;
#pragma unroll
        for (int i = 15; i >= 0; i--) {
            unsigned w0 = v4[i].x, w1 = v4[i].y, w2 = v4[i].z, w3 = v4[i].w;
            if (bin < 0) { acc += w3; if (acc >= TOPK) bin = i * 4 + 3; }
            if (bin < 0) { acc += w2; if (acc >= TOPK) bin = i * 4 + 2; }
            if (bin < 0) { acc += w1; if (acc >= TOPK) bin = i * 4 + 1; }
            if (bin < 0) { acc += w0; if (acc >= TOPK) bin = i * 4 + 0; }
        }
        g_thr[b] = ((unsigned)(t * 64 + bin)) << 16;
    }
}

// ---------------- K3: compact (warp-aggregated atomics) -------------------
__global__ void k_compact(const int* __restrict__ bidx, int N) {
    int p = blockIdx.x * 256 + threadIdx.x;
    unsigned long long key = 0ull;
    int b = -1;
    bool pred = false;
    if (p < N) {
        key = g_keyarr[p];
        b = bidx[p];
        pred = ((unsigned)(key >> 32) >= g_thr[b]);
    }
    const unsigned lane = threadIdx.x & 31;
#pragma unroll
    for (int bb = 0; bb < NUMB; bb++) {
        unsigned m = __ballot_sync(0xffffffffu, pred && (b == bb));
        if (m) {
            int leader = __ffs(m) - 1;
            int base = 0;
            if ((int)lane == leader) base = atomicAdd(&g_ccnt[bb], __popc(m));
            base = __shfl_sync(0xffffffffu, base, leader);
            if (pred && (b == bb)) {
                int slot = base + __popc(m & ((1u << lane) - 1u));
                if (slot < CAND) g_cand[bb][slot] = key;
            }
        }
    }
}

// ---------------- K4: PRECISE rescore + reg-head outputs ------------------
// warp per candidate. Score: compensated f32 -> double (exact ordering).
// Reg outputs: plain f32 tree (1e-3 value tolerance).
// Output key: score(32) | (0x3FFFF - idx)(18) | slot(12).
__global__ void __launch_bounds__(128) k_rescore(
        const float* __restrict__ feat,
        const float* __restrict__ Wc,
        const float* __restrict__ bc,
        const float* __restrict__ Wr,
        const float* __restrict__ br,
        int N) {
    __shared__ float swc0[256], swc1[256], sw8[256];
    __shared__ float sWr[256 * 8];
    for (int i = threadIdx.x; i < 256; i += 128) {
        swc0[i] = Wc[2 * i + 0];
        swc1[i] = Wc[2 * i + 1];
        sw8[i]  = Wr[9 * i + 8];
    }
    for (int i = threadIdx.x; i < 256 * 8; i += 128) {
        int f = i >> 3, o = i & 7;
        sWr[i] = Wr[f * 9 + o];
    }
    __syncthreads();

    const int b = blockIdx.y;
    const int warp = threadIdx.x >> 5;
    const int lane = threadIdx.x & 31;
    const int k = blockIdx.x * 4 + warp;

    unsigned long long key = g_cand[b][k];
    unsigned idx = ~(unsigned)(key & 0xffffffffu);
    bool valid = (idx < (unsigned)N);

    double d0 = 0.0, d1 = 0.0, d2 = 0.0;
    float ra[8];
#pragma unroll
    for (int o = 0; o < 8; o++) ra[o] = 0.0f;

    if (valid) {
        const float4* f4 = (const float4*)(feat + (size_t)idx * 256);
        float4 a  = f4[lane * 2 + 0];
        float4 c4 = f4[lane * 2 + 1];
        float fv[8] = {a.x, a.y, a.z, a.w, c4.x, c4.y, c4.z, c4.w};
        const float* wp[3] = {&swc0[lane * 8], &swc1[lane * 8], &sw8[lane * 8]};
        double* dp[3] = {&d0, &d1, &d2};
#pragma unroll
        for (int o = 0; o < 3; o++) {
            float s = 0.0f, comp = 0.0f;
#pragma unroll
            for (int c = 0; c < 8; c++) {
                float v = fv[c], w = wp[o][c];
                float p = __fmul_rn(v, w);
                float e = __fmaf_rn(v, w, -p);
                float t = __fadd_rn(s, p);
                float bv = __fadd_rn(t, -s);
                float c1 = __fadd_rn(s, -__fadd_rn(t, -bv));
                float c2 = __fadd_rn(p, -bv);
                comp = __fadd_rn(comp, __fadd_rn(c1, c2));
                comp = __fadd_rn(comp, e);
                s = t;
            }
            *dp[o] = (double)s + (double)comp;
        }
        // reg head: 8 outputs, plain f32
        const float* wr = &sWr[lane * 8 * 8];
#pragma unroll
        for (int c = 0; c < 8; c++) {
            float v = fv[c];
#pragma unroll
            for (int o = 0; o < 8; o++)
                ra[o] = __fmaf_rn(v, wr[c * 8 + o], ra[o]);
        }
    }
#pragma unroll
    for (int o = 16; o > 0; o >>= 1) {
        d0 += __shfl_xor_sync(0xffffffffu, d0, o);
        d1 += __shfl_xor_sync(0xffffffffu, d1, o);
        d2 += __shfl_xor_sync(0xffffffffu, d2, o);
    }
#pragma unroll
    for (int j = 0; j < 8; j++)
#pragma unroll
        for (int o = 16; o > 0; o >>= 1)
            ra[j] += __shfl_xor_sync(0xffffffffu, ra[j], o);

    if (lane < 8 && valid) {
        g_regs[b][k][lane] = __fadd_rn(ra[lane], br[lane]);
    }
    if (lane == 0) {
        unsigned long long outk = 0ull;
        if (valid) {
            double l0 = d0 + (double)bc[0];
            double l1 = d1 + (double)bc[1];
            double r8 = d2 + (double)br[8];
            double m  = fmax(l0, l1);
            double e0 = exp(l0 - m);
            double e1 = exp(l1 - m);
            double conf = e1 / (e0 + e1);
            double scr  = 1.0 / (1.0 + exp(-r8));
            float sf = (float)(conf * scr);
            outk = ((unsigned long long)__float_as_uint(sf) << 32) |
                   ((unsigned long long)(0x3FFFFu - idx) << 12) |
                   (unsigned long long)k;
        }
        g_prec[b][k] = outk;
    }
}

// ---------------- K5a: sort each 1024-chunk descending --------------------
__global__ void k_rank_leaf() {
    const int b = blockIdx.y;
    const int c = blockIdx.x;
    const int t = threadIdx.x;
    __shared__ unsigned long long s[1024];
    s[t] = g_prec[b][c * 1024 + t];

    for (unsigned k = 2; k <= 1024; k <<= 1) {
        for (unsigned jj = k >> 1; jj > 0; jj >>= 1) {
            __syncthreads();
            unsigned ixj = t ^ jj;
            if (ixj > (unsigned)t) {
                unsigned long long a = s[t], bb = s[ixj];
                bool desc = ((t & k) == 0);
                if (desc ? (a < bb) : (a > bb)) { s[t] = bb; s[ixj] = a; }
            }
        }
    }
    __syncthreads();
    g_prec[b][c * 1024 + t] = s[t];
}

// ---------------- K5b: merge chunk pairs -> top 1024 each -----------------
__global__ void k_rank_m1() {
    const int b = blockIdx.y;
    const int c = blockIdx.x;
    const int t = threadIdx.x;
    __shared__ unsigned long long s[2048];
    s[t]        = g_prec[b][(2 * c) * 1024 + t];
    s[2047 - t] = g_prec[b][(2 * c + 1) * 1024 + t];
    for (unsigned jj = 1024; jj > 0; jj >>= 1) {
        __syncthreads();
#pragma unroll
        for (int rr = 0; rr < 2; rr++) {
            unsigned tt = t + rr * 1024;
            unsigned ixj = tt ^ jj;
            if (ixj > tt) {
                unsigned long long a = s[tt], bb = s[ixj];
                if (a < bb) { s[tt] = bb; s[ixj] = a; }
            }
        }
    }
    __syncthreads();
    g_tmp[b][c * 1024 + t] = s[t];
}

// ---------------- K5c: final merge + box assembly -------------------------
__global__ void k_rank_m2f(const int* __restrict__ coor) {
    const int b = blockIdx.x;
    const int t = threadIdx.x;
    __shared__ unsigned long long s[2048];
    s[t]        = g_tmp[b][t];
    s[2047 - t] = g_tmp[b][1024 + t];
    for (unsigned jj = 1024; jj > 0; jj >>= 1) {
        __syncthreads();
#pragma unroll
        for (int rr = 0; rr < 2; rr++) {
            unsigned tt = t + rr * 1024;
            unsigned ixj = tt ^ jj;
            if (ixj > tt) {
                unsigned long long a = s[tt], bb = s[ixj];
                if (a < bb) { s[tt] = bb; s[ixj] = a; }
            }
        }
    }
    __syncthreads();
    unsigned long long key = s[t];
    g_sel[b][t] = key;

    float out[8];
    if (key != 0ull) {
        unsigned slot = (unsigned)(key & 0xFFFu);
        unsigned idx  = 0x3FFFFu - (unsigned)((key >> 12) & 0x3FFFFu);
        float4 ra = ((const float4*)g_regs[b][slot])[0];
        float4 rb = ((const float4*)g_regs[b][slot])[1];
        float cx = __fmul_rn((float)coor[(size_t)idx * 2 + 0], 0.8f);
        float cy = __fmul_rn((float)coor[(size_t)idx * 2 + 1], 0.8f);
        out[0] = __fadd_rn(cx, ra.x);
        out[1] = __fadd_rn(cy, ra.y);
        out[2] = ra.z;
        out[3] = expf(fminf(fmaxf(ra.w, -6.0f), 6.0f));
        out[4] = expf(fminf(fmaxf(rb.x, -6.0f), 6.0f));
        out[5] = expf(fminf(fmaxf(rb.y, -6.0f), 6.0f));
        out[6] = atan2f(rb.z, rb.w);
        out[7] = __uint_as_float((unsigned)(key >> 32));
    } else {
#pragma unroll
        for (int j = 0; j < 8; j++) out[j] = 0.0f;
    }
#pragma unroll
    for (int j = 0; j < 8; j++) g_boxes[b][t][j] = out[j];
}

// ---------------- K7: IoU suppression bitmask (parallel) ------------------
__global__ void k_mask() {
    const int b = blockIdx.y;
    const int j = threadIdx.x;
    __shared__ float sx1[PRE], sx2[PRE], sy1[PRE], sy2[PRE], sa[PRE];

    float x = g_boxes[b][j][0], y = g_boxes[b][j][1];
    float l = g_boxes[b][j][3], w = g_boxes[b][j][4];
    bool jv = (g_sel[b][j] != 0ull);
    if (jv) {
        float lh = __fmul_rn(l, 0.5f);
        float wh = __fmul_rn(w, 0.5f);
        sx1[j] = __fadd_rn(x, -lh); sx2[j] = __fadd_rn(x, lh);
        sy1[j] = __fadd_rn(y, -wh); sy2[j] = __fadd_rn(y, wh);
        sa[j]  = __fmul_rn(l, w);
    } else {
        sx1[j] = 1e30f; sx2[j] = -1e30f;
        sy1[j] = 1e30f; sy2[j] = -1e30f;
        sa[j]  = 0.0f;
    }
    __syncthreads();

    const int i0 = blockIdx.x * 32;
    const float X1 = sx1[j], X2 = sx2[j], Y1 = sy1[j], Y2 = sy2[j], A = sa[j];
    for (int ii = 0; ii < 32; ii++) {
        int i = i0 + ii;
        float ix = fmaxf(__fadd_rn(fminf(sx2[i], X2), -fmaxf(sx1[i], X1)), 0.0f);
        float iy = fmaxf(__fadd_rn(fminf(sy2[i], Y2), -fmaxf(sy1[i], Y1)), 0.0f);
        float inter = __fmul_rn(ix, iy);
        float uni = __fadd_rn(__fadd_rn(sa[i], A), -inter);
        float iou = __fdiv_rn(inter, fmaxf(uni, 1e-6f));
        bool s = (j > i) && (iou > 0.1f);
        unsigned bal = __ballot_sync(0xffffffffu, s);
        if ((j & 31) == 0) {
            g_mask[b][i][j >> 5] = bal;
            if (bal) atomicOr(&g_rowflag[b][i >> 5], 1u << (i & 31));
        }
    }
}

// ---------------- K8: serial greedy scan (sparse rows only) + outputs -----
__global__ void k_scan_out(float* __restrict__ dout, int out_size) {
    const int b = blockIdx.x;
    const int t = threadIdx.x;
    __shared__ unsigned srem[32];

    if (t < 32) {
        unsigned rem = 0;
        unsigned flags = g_rowflag[b][t];
        for (int w = 0; w < 32; w++) {
            unsigned fw = __shfl_sync(0xffffffffu, flags, w);
            while (fw) {
                int bp = __ffs(fw) - 1;
                fw &= fw - 1;
                int i = w * 32 + bp;
                unsigned owner = __shfl_sync(0xffffffffu, rem, i >> 5);
                if (!((owner >> (i & 31)) & 1u)) {
                    rem |= g_mask[b][i][t];
                }
            }
        }
        srem[t] = rem;
    }
    __syncthreads();

    bool jv = (g_sel[b][t] != 0ull);
    bool keep = jv && !((srem[t >> 5] >> (t & 31)) & 1u);
    float kf = keep ? 1.0f : 0.0f;

    int obase = (b * PRE + t) * 8;
#pragma unroll
    for (int c = 0; c < 8; c++) {
        if (obase + c < out_size) dout[obase + c] = g_boxes[b][t][c] * kf;
    }
    int lbpos = NUMB * PRE * 8 + b * PRE + t;
    if (lbpos < out_size) dout[lbpos] = 0.0f;
    int kppos = NUMB * PRE * 9 + b * PRE + t;
    if (kppos < out_size) dout[kppos] = kf;
}

// ---------------- launcher ----------------
extern "C" void kernel_launch(void* const* d_in, const int* in_sizes, int n_in,
                              void* d_out, int out_size) {
    const float* feat  = (const float*)d_in[0];
    const int*   bidx  = (const int*)d_in[1];
    const int*   coor  = (const int*)d_in[2];
    const float* Wc    = (const float*)d_in[3];
    const float* bc    = (const float*)d_in[4];
    const float* Wr    = (const float*)d_in[5];
    const float* br    = (const float*)d_in[6];
    float* out = (float*)d_out;

    const int N = in_sizes[1];

    k_zero_all<<<(HBINS + NUMB * CAND / 2 + NUMB * 33 + 255) / 256, 256>>>();
    k_score<<<(N + 255) / 256, 256>>>(feat, bidx, Wc, bc, Wr, br, N);
    k_thresh<<<NUMB, 1024>>>();
    k_compact<<<(N + 255) / 256, 256>>>(bidx, N);
    k_rescore<<<dim3(CAND / 4, NUMB), 128>>>(feat, Wc, bc, Wr, br, N);
    k_rank_leaf<<<dim3(4, NUMB), 1024>>>();
    k_rank_m1<<<dim3(2, NUMB), 1024>>>();
    k_rank_m2f<<<NUMB, 1024>>>(coor);
    k_mask<<<dim3(PRE / 32, NUMB), 1024>>>();
    k_scan_out<<<NUMB, 1024>>>(out, out_size);
}